// round 1
// baseline (speedup 1.0000x reference)
#include <cuda_runtime.h>
#include <math.h>

// Problem constants
#define BB   2
#define NN   2048
#define RRoi 128
#define CINv 256
#define NSv  16
#define C1v  128
#define RADv 0.3f
#define EPSv 1e-5f
#define FEATS_SZ (BB*C1v*NN)          // 524288
#define GRID_SZ  (BB*RRoi*125*C1v)    // 4096000

// ---------------- scratch (no allocations allowed) ----------------
__device__ int   g_idx[BB*NN*NSv];
__device__ float g_Gt[BB*NN*256];        // [b][j][o]  (o contiguous)
__device__ float g_hmax[BB*256*NN];      // [b][o][n]
__device__ float g_h2[BB*C1v*NN];        // [b][o][n]
__device__ float g_h3[BB*C1v*NN];        // [b][o][n]
__device__ float g_featsT[BB*NN*C1v];    // [b][n][c]
__device__ float g_WfT[256*256];         // [c][o]
__device__ float g_WxT[3*256];           // [k][o]
__device__ float g_W1T[256*C1v];         // [c][o]
__device__ float g_W2T[C1v*C1v];         // [c][o]
// stats: [0:256) sum1 [256:512) sq1 [512:640) sum2 [640:768) sq2 [768:896) sum3 [896:1024) sq3
__device__ float g_stats[1024];
__device__ float g_sc1[256], g_sh1[256];
__device__ float g_sc2[C1v], g_sh2[C1v];
__device__ float g_sc3[C1v], g_sh3[C1v];

// ---------------- weight transposes ----------------
__global__ void k_prep(const float* __restrict__ Wm, const float* __restrict__ W1,
                       const float* __restrict__ W2) {
    int id = blockIdx.x * 256 + threadIdx.x;
    if (id < 65536) {                      // WfT[c][o] = Wm[o][3+c]
        int o = id & 255, c = id >> 8;
        g_WfT[id] = Wm[o * 259 + 3 + c];
    } else if (id < 66304) {               // WxT[k][o] = Wm[o][k]
        int t = id - 65536; int o = t & 255, k = t >> 8;
        g_WxT[t] = Wm[o * 259 + k];
    } else if (id < 99072) {               // W1T[c][o]
        int t = id - 66304; int o = t & 127, c = t >> 7;
        g_W1T[t] = W1[o * 256 + c];
    } else if (id < 115456) {              // W2T[c][o]
        int t = id - 99072; int o = t & 127, c = t >> 7;
        g_W2T[t] = W2[o * 128 + c];
    }
}

// ---------------- neighbor search: first 16 ascending indices with d2 < r2 ----------------
__global__ void k_neigh(const float* __restrict__ pts) {
    __shared__ float sx[NN], sy[NN], sz[NN];
    int b = blockIdx.y;
    const float* P = pts + (size_t)b * NN * 3;
    for (int j = threadIdx.x; j < NN; j += blockDim.x) {
        sx[j] = P[j * 3 + 0]; sy[j] = P[j * 3 + 1]; sz[j] = P[j * 3 + 2];
    }
    __syncthreads();
    int i = blockIdx.x * blockDim.x + threadIdx.x;
    float xi = sx[i], yi = sy[i], zi = sz[i];
    int lst[NSv];
    int cnt = 0;
    const float r2 = RADv * RADv;
    for (int j = 0; j < NN; j++) {
        float dx = sx[j] - xi, dy = sy[j] - yi, dz = sz[j] - zi;
        float d2 = dx * dx + dy * dy + dz * dz;
        if (d2 < r2) {
            lst[cnt++] = j;
            if (cnt == NSv) break;
        }
    }
    int f0 = lst[0];                         // self always qualifies -> cnt>=1
    for (int s = cnt; s < NSv; s++) lst[s] = f0;
    int base = (b * NN + i) * NSv;
    #pragma unroll
    for (int s = 0; s < NSv; s++) g_idx[base + s] = lst[s];
}

// ---------------- GEMM: Gt[b][j][o] = sum_c feat[b][c][j] * WfT[c][o] ----------------
__global__ void k_gemmG(const float* __restrict__ feat) {
    __shared__ float As[16][64];  // [kk][j]
    __shared__ float Bs[16][64];  // [kk][o]
    int b = blockIdx.z;
    int j0 = blockIdx.x * 64, o0 = blockIdx.y * 64;
    int tid = threadIdx.x;
    int tx = tid & 15, ty = tid >> 4;
    float acc[4][4] = {};
    for (int k0 = 0; k0 < CINv; k0 += 16) {
        #pragma unroll
        for (int q = 0; q < 4; q++) {
            int l = tid + q * 256;
            int kk = l >> 6, cc = l & 63;
            As[kk][cc] = feat[(size_t)(b * CINv + k0 + kk) * NN + j0 + cc];
            Bs[kk][cc] = g_WfT[(k0 + kk) * 256 + o0 + cc];
        }
        __syncthreads();
        #pragma unroll
        for (int kk = 0; kk < 16; kk++) {
            float aj[4], ao[4];
            #pragma unroll
            for (int i = 0; i < 4; i++) aj[i] = As[kk][ty + i * 16];
            #pragma unroll
            for (int i = 0; i < 4; i++) ao[i] = Bs[kk][tx + i * 16];
            #pragma unroll
            for (int i = 0; i < 4; i++)
                #pragma unroll
                for (int jn = 0; jn < 4; jn++) acc[i][jn] += aj[i] * ao[jn];
        }
        __syncthreads();
    }
    #pragma unroll
    for (int i = 0; i < 4; i++)
        #pragma unroll
        for (int jn = 0; jn < 4; jn++)
            g_Gt[(size_t)(b * NN + j0 + ty + i * 16) * 256 + o0 + tx + jn * 16] = acc[i][jn];
}

// ---------------- gather + xyz MLP + max over samples + BN1 stats ----------------
#define PPB 16
__global__ void k_gathermax(const float* __restrict__ pts) {
    __shared__ int   sj[PPB * NSv];
    __shared__ float srx[PPB * NSv], sry[PPB * NSv], srz[PPB * NSv];
    __shared__ float stile[256 * (PPB + 1)];
    int b = blockIdx.y;
    int n0 = blockIdx.x * PPB;
    int tid = threadIdx.x;
    {
        int p = tid >> 4, s = tid & 15;
        int n = n0 + p;
        int j = g_idx[(b * NN + n) * NSv + s];
        sj[tid] = j;
        const float* P = pts + (size_t)b * NN * 3;
        srx[tid] = (P[j * 3 + 0] - P[n * 3 + 0]) / RADv;
        sry[tid] = (P[j * 3 + 1] - P[n * 3 + 1]) / RADv;
        srz[tid] = (P[j * 3 + 2] - P[n * 3 + 2]) / RADv;
    }
    __syncthreads();
    int o = tid;
    float w0 = g_WxT[o], w1 = g_WxT[256 + o], w2 = g_WxT[512 + o];
    float ls = 0.f, lq = 0.f;
    const float* Gb = g_Gt + (size_t)b * NN * 256;
    for (int p = 0; p < PPB; p++) {
        float m = -3.4e38f;
        #pragma unroll
        for (int s = 0; s < NSv; s++) {
            int e = p * NSv + s;
            int j = sj[e];
            float v = Gb[(size_t)j * 256 + o] + w0 * srx[e] + w1 * sry[e] + w2 * srz[e];
            m = fmaxf(m, v);
            ls += v;
            lq += v * v;
        }
        stile[o * (PPB + 1) + p] = m;
    }
    __syncthreads();
    // coalesced-ish write of the 256 x PPB tile into hmax[b][o][n]
    for (int r = 0; r < 256; r += 16) {
        int row = r + (tid >> 4);
        int col = tid & 15;
        g_hmax[(size_t)(b * 256 + row) * NN + n0 + col] = stile[row * (PPB + 1) + col];
    }
    atomicAdd(&g_stats[o], ls);
    atomicAdd(&g_stats[256 + o], lq);
}

// ---------------- finalize BN params ----------------
__global__ void k_fin(const float* __restrict__ g, const float* __restrict__ bt,
                      int C, float invcnt, int soff, int which) {
    int o = threadIdx.x;
    if (o >= C) return;
    float m = g_stats[soff + o] * invcnt;
    float v = g_stats[soff + C + o] * invcnt - m * m;
    float sc = g[o] / sqrtf(v + EPSv);
    float sh = bt[o] - m * sc;
    if (which == 0) { g_sc1[o] = sc; g_sh1[o] = sh; }
    else if (which == 1) { g_sc2[o] = sc; g_sh2[o] = sh; }
    else { g_sc3[o] = sc; g_sh3[o] = sh; }
}

// ---------------- GEMM1: h2[b][o][n] = b1[o] + sum_c relu(bn1(hmax[b][c][n])) * W1T[c][o] ----------------
__global__ void k_gemm1(const float* __restrict__ b1) {
    __shared__ float As[16][64];  // [kk][n]
    __shared__ float Bs[16][64];  // [kk][o]
    int b = blockIdx.z;
    int n0 = blockIdx.x * 64, o0 = blockIdx.y * 64;
    int tid = threadIdx.x;
    int tx = tid & 15, ty = tid >> 4;
    float acc[4][4] = {};
    for (int k0 = 0; k0 < 256; k0 += 16) {
        #pragma unroll
        for (int q = 0; q < 4; q++) {
            int l = tid + q * 256;
            int kk = l >> 6, cc = l & 63;
            float v = g_hmax[(size_t)(b * 256 + k0 + kk) * NN + n0 + cc];
            As[kk][cc] = fmaxf(v * g_sc1[k0 + kk] + g_sh1[k0 + kk], 0.f);
            Bs[kk][cc] = g_W1T[(k0 + kk) * C1v + o0 + cc];
        }
        __syncthreads();
        #pragma unroll
        for (int kk = 0; kk < 16; kk++) {
            float ao[4], an[4];
            #pragma unroll
            for (int i = 0; i < 4; i++) ao[i] = Bs[kk][ty + i * 16];
            #pragma unroll
            for (int i = 0; i < 4; i++) an[i] = As[kk][tx + i * 16];
            #pragma unroll
            for (int i = 0; i < 4; i++)
                #pragma unroll
                for (int jn = 0; jn < 4; jn++) acc[i][jn] += ao[i] * an[jn];
        }
        __syncthreads();
    }
    #pragma unroll
    for (int i = 0; i < 4; i++) {
        int oy = o0 + ty + i * 16;
        float bias = b1[oy];
        #pragma unroll
        for (int jn = 0; jn < 4; jn++)
            g_h2[(size_t)(b * C1v + oy) * NN + n0 + tx + jn * 16] = acc[i][jn] + bias;
    }
}

// ---------------- GEMM2: h3 = b2 + W2 @ relu(bn2(h2)) ----------------
__global__ void k_gemm2(const float* __restrict__ b2) {
    __shared__ float As[16][64];
    __shared__ float Bs[16][64];
    int b = blockIdx.z;
    int n0 = blockIdx.x * 64, o0 = blockIdx.y * 64;
    int tid = threadIdx.x;
    int tx = tid & 15, ty = tid >> 4;
    float acc[4][4] = {};
    for (int k0 = 0; k0 < 128; k0 += 16) {
        #pragma unroll
        for (int q = 0; q < 4; q++) {
            int l = tid + q * 256;
            int kk = l >> 6, cc = l & 63;
            float v = g_h2[(size_t)(b * C1v + k0 + kk) * NN + n0 + cc];
            As[kk][cc] = fmaxf(v * g_sc2[k0 + kk] + g_sh2[k0 + kk], 0.f);
            Bs[kk][cc] = g_W2T[(k0 + kk) * C1v + o0 + cc];
        }
        __syncthreads();
        #pragma unroll
        for (int kk = 0; kk < 16; kk++) {
            float ao[4], an[4];
            #pragma unroll
            for (int i = 0; i < 4; i++) ao[i] = Bs[kk][ty + i * 16];
            #pragma unroll
            for (int i = 0; i < 4; i++) an[i] = As[kk][tx + i * 16];
            #pragma unroll
            for (int i = 0; i < 4; i++)
                #pragma unroll
                for (int jn = 0; jn < 4; jn++) acc[i][jn] += ao[i] * an[jn];
        }
        __syncthreads();
    }
    #pragma unroll
    for (int i = 0; i < 4; i++) {
        int oy = o0 + ty + i * 16;
        float bias = b2[oy];
        #pragma unroll
        for (int jn = 0; jn < 4; jn++)
            g_h3[(size_t)(b * C1v + oy) * NN + n0 + tx + jn * 16] = acc[i][jn] + bias;
    }
}

// ---------------- per-channel stats over (b, n) for h2 / h3 ----------------
__global__ void k_stats(int which) {
    const float* h = (which == 1) ? g_h2 : g_h3;
    int off = (which == 1) ? 512 : 768;
    int o = blockIdx.x;
    __shared__ float ra[256], rq[256];
    float a = 0.f, q = 0.f;
    for (int t = threadIdx.x; t < BB * NN; t += 256) {
        int b = t >> 11, n = t & 2047;
        float v = h[(size_t)(b * C1v + o) * NN + n];
        a += v; q += v * v;
    }
    ra[threadIdx.x] = a; rq[threadIdx.x] = q;
    __syncthreads();
    for (int w = 128; w > 0; w >>= 1) {
        if (threadIdx.x < w) { ra[threadIdx.x] += ra[threadIdx.x + w]; rq[threadIdx.x] += rq[threadIdx.x + w]; }
        __syncthreads();
    }
    if (threadIdx.x == 0) { g_stats[off + o] = ra[0]; g_stats[off + C1v + o] = rq[0]; }
}

// ---------------- final feats: write output [b][c][n] and transposed scratch [b][n][c] ----------------
__global__ void k_feats(float* __restrict__ out) {
    int e = blockIdx.x * 256 + threadIdx.x;   // 0 .. 524287
    int b = e >> 18;                          // / (128*2048)
    int rem = e & ((C1v * NN) - 1);
    int o = rem >> 11;                        // / 2048
    int n = rem & 2047;
    float v = g_h3[e];
    float f = fmaxf(v * g_sc3[o] + g_sh3[o], 0.f);
    out[e] = f;
    g_featsT[(size_t)(b * NN + n) * C1v + o] = f;
}

// ---------------- RoI voxel max-pool ----------------
__global__ void k_roipool(const float* __restrict__ pts, const float* __restrict__ rois,
                          float* __restrict__ out) {
    int br = blockIdx.x;
    int b = br >> 7;
    const float* q = rois + (size_t)br * 7;
    float cx = q[0], cy = q[1], cz = q[2];
    float hx = q[3] * 0.5f, hy = q[4] * 0.5f, hz = q[5] * 0.5f;
    float co = cosf(q[6]), si = sinf(q[6]);
    __shared__ int cnt;
    __shared__ int lst[2048];
    if (threadIdx.x == 0) cnt = 0;
    __syncthreads();
    const float* P = pts + (size_t)b * NN * 3;
    for (int n = threadIdx.x; n < NN; n += 128) {
        float rx = P[n * 3 + 0] - cx;
        float ry = P[n * 3 + 1] - cy;
        float rz = P[n * 3 + 2] - cz;
        float lx = rx * co + ry * si;
        float ly = -rx * si + ry * co;
        float lz = rz;
        if (fabsf(lx) < hx && fabsf(ly) < hy && fabsf(lz) < hz) {
            int v0 = (int)fminf(fmaxf(floorf((lx + hx) / (2.f * hx) * 5.f), 0.f), 4.f);
            int v1 = (int)fminf(fmaxf(floorf((ly + hy) / (2.f * hy) * 5.f), 0.f), 4.f);
            int v2 = (int)fminf(fmaxf(floorf((lz + hz) / (2.f * hz) * 5.f), 0.f), 4.f);
            int vox = (v0 * 5 + v1) * 5 + v2;
            int pos = atomicAdd(&cnt, 1);
            lst[pos] = (vox << 12) | n;
        }
    }
    __syncthreads();
    int t = threadIdx.x;
    float* og = out + FEATS_SZ + (size_t)br * 125 * C1v;
    int m = cnt;
    for (int e = 0; e < m; e++) {
        int pk = lst[e];
        int n = pk & 4095;
        int vox = pk >> 12;
        float val = g_featsT[(size_t)(b * NN + n) * C1v + t];
        atomicMax((int*)(og + vox * C1v + t), __float_as_int(val));
    }
}

// ---------------- launch ----------------
extern "C" void kernel_launch(void* const* d_in, const int* in_sizes, int n_in,
                              void* d_out, int out_size) {
    const float* pts    = (const float*)d_in[0];
    const float* feat   = (const float*)d_in[1];
    const float* rois   = (const float*)d_in[2];
    const float* W_mlp  = (const float*)d_in[3];
    const float* g_mlp  = (const float*)d_in[4];
    const float* btm    = (const float*)d_in[5];
    const float* W1     = (const float*)d_in[6];
    const float* b1     = (const float*)d_in[7];
    const float* g1     = (const float*)d_in[8];
    const float* bt1    = (const float*)d_in[9];
    const float* W2     = (const float*)d_in[10];
    const float* b2     = (const float*)d_in[11];
    const float* g2     = (const float*)d_in[12];
    const float* bt2    = (const float*)d_in[13];
    float* out = (float*)d_out;

    void* statsPtr = nullptr;
    cudaGetSymbolAddress(&statsPtr, g_stats);
    cudaMemsetAsync(statsPtr, 0, 1024 * sizeof(float), 0);
    cudaMemsetAsync(out + FEATS_SZ, 0, (size_t)GRID_SZ * sizeof(float), 0);

    k_prep<<<452, 256>>>(W_mlp, W1, W2);
    k_neigh<<<dim3(NN / 256, BB), 256>>>(pts);
    k_gemmG<<<dim3(NN / 64, 256 / 64, BB), 256>>>(feat);
    k_gathermax<<<dim3(NN / PPB, BB), 256>>>(pts);
    k_fin<<<1, 256>>>(g_mlp, btm, 256, 1.f / 65536.f, 0, 0);
    k_gemm1<<<dim3(NN / 64, C1v / 64, BB), 256>>>(b1);
    k_stats<<<C1v, 256>>>(1);
    k_fin<<<1, 128>>>(g1, bt1, 128, 1.f / 4096.f, 512, 1);
    k_gemm2<<<dim3(NN / 64, C1v / 64, BB), 256>>>(b2);
    k_stats<<<C1v, 256>>>(2);
    k_fin<<<1, 128>>>(g2, bt2, 128, 1.f / 4096.f, 768, 2);
    k_feats<<<FEATS_SZ / 256, 256>>>(out);
    k_roipool<<<BB * RRoi, 128>>>(pts, rois, out);
}

// round 2
// speedup vs baseline: 1.9608x; 1.9608x over previous
#include <cuda_runtime.h>
#include <math.h>

// Problem constants
#define BB   2
#define NN   2048
#define RRoi 128
#define CINv 256
#define NSv  16
#define C1v  128
#define RADv 0.3f
#define EPSv 1e-5f
#define FEATS_SZ (BB*C1v*NN)          // 524288
#define GRID_SZ  (BB*RRoi*125*C1v)    // 4096000

// ---------------- scratch ----------------
__device__ int   g_idx[BB*NN*NSv];
__device__ float g_Gt[BB*NN*256];        // [b][j][o]  (o contiguous)
__device__ float g_hmax[BB*256*NN];      // [b][o][n]
__device__ float g_h2[BB*C1v*NN];        // [b][o][n]
__device__ float g_h3[BB*C1v*NN];        // [b][o][n]
__device__ float g_featsT[BB*NN*C1v];    // [b][n][c]
__device__ float g_WfT[256*256];         // [c][o]
__device__ float g_WxT[3*256];           // [k][o]
__device__ float g_W1T[256*C1v];         // [c][o]
__device__ float g_W2T[C1v*C1v];         // [c][o]
// stats: [0:256) sum1 [256:512) sq1 [512:640) sum2 [640:768) sq2 [768:896) sum3 [896:1024) sq3
__device__ float g_stats[1024];

// ---------------- weight transposes ----------------
__global__ void k_prep(const float* __restrict__ Wm, const float* __restrict__ W1,
                       const float* __restrict__ W2) {
    int id = blockIdx.x * 256 + threadIdx.x;
    if (id < 65536) {                      // WfT[c][o] = Wm[o][3+c]
        int o = id & 255, c = id >> 8;
        g_WfT[id] = Wm[o * 259 + 3 + c];
    } else if (id < 66304) {               // WxT[k][o] = Wm[o][k]
        int t = id - 65536; int o = t & 255, k = t >> 8;
        g_WxT[t] = Wm[o * 259 + k];
    } else if (id < 99072) {               // W1T[c][o]
        int t = id - 66304; int o = t & 127, c = t >> 7;
        g_W1T[t] = W1[o * 256 + c];
    } else if (id < 115456) {              // W2T[c][o]
        int t = id - 99072; int o = t & 127, c = t >> 7;
        g_W2T[t] = W2[o * 128 + c];
    }
}

// ---------------- neighbor search: warp-per-point ballot scan ----------------
__global__ void k_neigh(const float* __restrict__ pts) {
    __shared__ float sx[NN], sy[NN], sz[NN];
    int b = blockIdx.y;
    const float* P = pts + (size_t)b * NN * 3;
    for (int j = threadIdx.x; j < NN; j += 256) {
        sx[j] = P[j * 3 + 0]; sy[j] = P[j * 3 + 1]; sz[j] = P[j * 3 + 2];
    }
    __syncthreads();
    int warp = threadIdx.x >> 5, lane = threadIdx.x & 31;
    int i = blockIdx.x * 8 + warp;
    float xi = sx[i], yi = sy[i], zi = sz[i];
    int base = (b * NN + i) * NSv;
    const float r2 = RADv * RADv;
    int cnt = 0, f0 = -1;
    for (int j0 = 0; j0 < NN; j0 += 32) {
        int j = j0 + lane;
        float dx = sx[j] - xi, dy = sy[j] - yi, dz = sz[j] - zi;
        bool q = (dx * dx + dy * dy + dz * dz) < r2;
        unsigned m = __ballot_sync(0xffffffffu, q);
        if (m) {
            if (f0 < 0) f0 = j0 + __ffs(m) - 1;
            int pos = cnt + __popc(m & ((1u << lane) - 1u));
            if (q && pos < NSv) g_idx[base + pos] = j;
            cnt += __popc(m);
            if (cnt >= NSv) break;
        }
    }
    if (cnt < NSv) {
        for (int s = cnt + lane; s < NSv; s += 32) g_idx[base + s] = f0;
    }
}

// ---------------- GEMM: Gt[b][j][o] = sum_c feat[b][c][j] * WfT[c][o] ----------------
__global__ void k_gemmG(const float* __restrict__ feat) {
    __shared__ float As[16][64];  // [kk][j]
    __shared__ float Bs[16][64];  // [kk][o]
    int b = blockIdx.z;
    int j0 = blockIdx.x * 64, o0 = blockIdx.y * 64;
    int tid = threadIdx.x;
    int tx = tid & 15, ty = tid >> 4;
    float acc[4][4] = {};
    for (int k0 = 0; k0 < CINv; k0 += 16) {
        #pragma unroll
        for (int q = 0; q < 4; q++) {
            int l = tid + q * 256;
            int kk = l >> 6, cc = l & 63;
            As[kk][cc] = feat[(size_t)(b * CINv + k0 + kk) * NN + j0 + cc];
            Bs[kk][cc] = g_WfT[(k0 + kk) * 256 + o0 + cc];
        }
        __syncthreads();
        #pragma unroll
        for (int kk = 0; kk < 16; kk++) {
            float4 a4 = *(const float4*)&As[kk][ty * 4];
            float4 b4 = *(const float4*)&Bs[kk][tx * 4];
            float av[4] = {a4.x, a4.y, a4.z, a4.w};
            float bv[4] = {b4.x, b4.y, b4.z, b4.w};
            #pragma unroll
            for (int i = 0; i < 4; i++)
                #pragma unroll
                for (int q = 0; q < 4; q++) acc[i][q] += av[i] * bv[q];
        }
        __syncthreads();
    }
    #pragma unroll
    for (int i = 0; i < 4; i++) {
        float4 st = make_float4(acc[i][0], acc[i][1], acc[i][2], acc[i][3]);
        *(float4*)&g_Gt[(size_t)(b * NN + j0 + ty * 4 + i) * 256 + o0 + tx * 4] = st;
    }
}

// ---------------- gather + xyz MLP + max over samples + BN1 stats ----------------
#define PPB 8
__global__ void k_gathermax(const float* __restrict__ pts) {
    __shared__ int   sj[PPB * NSv];
    __shared__ float srx[PPB * NSv], sry[PPB * NSv], srz[PPB * NSv];
    __shared__ float stile[256 * (PPB + 1)];
    int b = blockIdx.y;
    int n0 = blockIdx.x * PPB;
    int tid = threadIdx.x;
    if (tid < PPB * NSv) {
        int p = tid >> 4, s = tid & 15;
        int n = n0 + p;
        int j = g_idx[(b * NN + n) * NSv + s];
        sj[tid] = j;
        const float* P = pts + (size_t)b * NN * 3;
        srx[tid] = (P[j * 3 + 0] - P[n * 3 + 0]) / RADv;
        sry[tid] = (P[j * 3 + 1] - P[n * 3 + 1]) / RADv;
        srz[tid] = (P[j * 3 + 2] - P[n * 3 + 2]) / RADv;
    }
    __syncthreads();
    int o = tid;
    float w0 = g_WxT[o], w1 = g_WxT[256 + o], w2 = g_WxT[512 + o];
    float ls = 0.f, lq = 0.f;
    const float* Gb = g_Gt + (size_t)b * NN * 256;
    #pragma unroll
    for (int p = 0; p < PPB; p++) {
        float m = -3.4e38f;
        #pragma unroll
        for (int s = 0; s < NSv; s++) {
            int e = p * NSv + s;
            int j = sj[e];
            float v = Gb[(size_t)j * 256 + o] + w0 * srx[e] + w1 * sry[e] + w2 * srz[e];
            m = fmaxf(m, v);
            ls += v;
            lq += v * v;
        }
        stile[o * (PPB + 1) + p] = m;
    }
    __syncthreads();
    #pragma unroll
    for (int r = 0; r < 256; r += 32) {
        int row = r + (tid >> 3);
        int col = tid & 7;
        g_hmax[(size_t)(b * 256 + row) * NN + n0 + col] = stile[row * (PPB + 1) + col];
    }
    atomicAdd(&g_stats[o], ls);
    atomicAdd(&g_stats[256 + o], lq);
}

// ---------------- GEMM1: h2 = b1 + W1 @ relu(bn1(hmax)), fused BN2 stats ----------------
__global__ void k_gemm1(const float* __restrict__ gm, const float* __restrict__ btm,
                        const float* __restrict__ b1) {
    __shared__ float As[16][64];  // [kk][n]
    __shared__ float Bs[16][64];  // [kk][o]
    __shared__ float ssc[256], ssh[256];
    int b = blockIdx.z;
    int n0 = blockIdx.x * 64, o0 = blockIdx.y * 64;
    int tid = threadIdx.x;
    int tx = tid & 15, ty = tid >> 4;
    {
        float m = g_stats[tid] * (1.f / 65536.f);
        float v = g_stats[256 + tid] * (1.f / 65536.f) - m * m;
        float sc = gm[tid] * rsqrtf(v + EPSv);
        ssc[tid] = sc; ssh[tid] = btm[tid] - m * sc;
    }
    __syncthreads();
    float acc[4][4] = {};
    for (int k0 = 0; k0 < 256; k0 += 16) {
        #pragma unroll
        for (int q = 0; q < 4; q++) {
            int l = tid + q * 256;
            int kk = l >> 6, cc = l & 63;
            float v = g_hmax[(size_t)(b * 256 + k0 + kk) * NN + n0 + cc];
            As[kk][cc] = fmaxf(v * ssc[k0 + kk] + ssh[k0 + kk], 0.f);
            Bs[kk][cc] = g_W1T[(k0 + kk) * C1v + o0 + cc];
        }
        __syncthreads();
        #pragma unroll
        for (int kk = 0; kk < 16; kk++) {
            float4 o4 = *(const float4*)&Bs[kk][ty * 4];
            float4 n4 = *(const float4*)&As[kk][tx * 4];
            float ov[4] = {o4.x, o4.y, o4.z, o4.w};
            float nv[4] = {n4.x, n4.y, n4.z, n4.w};
            #pragma unroll
            for (int i = 0; i < 4; i++)
                #pragma unroll
                for (int q = 0; q < 4; q++) acc[i][q] += ov[i] * nv[q];
        }
        __syncthreads();
    }
    float psum[4], psq[4];
    #pragma unroll
    for (int i = 0; i < 4; i++) {
        int oy = o0 + ty * 4 + i;
        float bias = b1[oy];
        float s = 0.f, q = 0.f;
        #pragma unroll
        for (int jn = 0; jn < 4; jn++) {
            float h = acc[i][jn] + bias;
            acc[i][jn] = h; s += h; q += h * h;
        }
        psum[i] = s; psq[i] = q;
        float4 st = make_float4(acc[i][0], acc[i][1], acc[i][2], acc[i][3]);
        *(float4*)&g_h2[(size_t)(b * C1v + oy) * NN + n0 + tx * 4] = st;
    }
    // reduce over the 16 tx lanes (consecutive within warp), lane tx==0 commits
    #pragma unroll
    for (int i = 0; i < 4; i++) {
        #pragma unroll
        for (int off = 8; off > 0; off >>= 1) {
            psum[i] += __shfl_down_sync(0xffffffffu, psum[i], off, 16);
            psq[i]  += __shfl_down_sync(0xffffffffu, psq[i],  off, 16);
        }
    }
    if (tx == 0) {
        #pragma unroll
        for (int i = 0; i < 4; i++) {
            int oy = o0 + ty * 4 + i;
            atomicAdd(&g_stats[512 + oy], psum[i]);
            atomicAdd(&g_stats[640 + oy], psq[i]);
        }
    }
}

// ---------------- GEMM2: h3 = b2 + W2 @ relu(bn2(h2)), fused BN3 stats ----------------
__global__ void k_gemm2(const float* __restrict__ g1, const float* __restrict__ bt1,
                        const float* __restrict__ b2) {
    __shared__ float As[16][64];
    __shared__ float Bs[16][64];
    __shared__ float ssc[128], ssh[128];
    int b = blockIdx.z;
    int n0 = blockIdx.x * 64, o0 = blockIdx.y * 64;
    int tid = threadIdx.x;
    int tx = tid & 15, ty = tid >> 4;
    if (tid < 128) {
        float m = g_stats[512 + tid] * (1.f / 4096.f);
        float v = g_stats[640 + tid] * (1.f / 4096.f) - m * m;
        float sc = g1[tid] * rsqrtf(v + EPSv);
        ssc[tid] = sc; ssh[tid] = bt1[tid] - m * sc;
    }
    __syncthreads();
    float acc[4][4] = {};
    for (int k0 = 0; k0 < 128; k0 += 16) {
        #pragma unroll
        for (int q = 0; q < 4; q++) {
            int l = tid + q * 256;
            int kk = l >> 6, cc = l & 63;
            float v = g_h2[(size_t)(b * C1v + k0 + kk) * NN + n0 + cc];
            As[kk][cc] = fmaxf(v * ssc[k0 + kk] + ssh[k0 + kk], 0.f);
            Bs[kk][cc] = g_W2T[(k0 + kk) * C1v + o0 + cc];
        }
        __syncthreads();
        #pragma unroll
        for (int kk = 0; kk < 16; kk++) {
            float4 o4 = *(const float4*)&Bs[kk][ty * 4];
            float4 n4 = *(const float4*)&As[kk][tx * 4];
            float ov[4] = {o4.x, o4.y, o4.z, o4.w};
            float nv[4] = {n4.x, n4.y, n4.z, n4.w};
            #pragma unroll
            for (int i = 0; i < 4; i++)
                #pragma unroll
                for (int q = 0; q < 4; q++) acc[i][q] += ov[i] * nv[q];
        }
        __syncthreads();
    }
    float psum[4], psq[4];
    #pragma unroll
    for (int i = 0; i < 4; i++) {
        int oy = o0 + ty * 4 + i;
        float bias = b2[oy];
        float s = 0.f, q = 0.f;
        #pragma unroll
        for (int jn = 0; jn < 4; jn++) {
            float h = acc[i][jn] + bias;
            acc[i][jn] = h; s += h; q += h * h;
        }
        psum[i] = s; psq[i] = q;
        float4 st = make_float4(acc[i][0], acc[i][1], acc[i][2], acc[i][3]);
        *(float4*)&g_h3[(size_t)(b * C1v + oy) * NN + n0 + tx * 4] = st;
    }
    #pragma unroll
    for (int i = 0; i < 4; i++) {
        #pragma unroll
        for (int off = 8; off > 0; off >>= 1) {
            psum[i] += __shfl_down_sync(0xffffffffu, psum[i], off, 16);
            psq[i]  += __shfl_down_sync(0xffffffffu, psq[i],  off, 16);
        }
    }
    if (tx == 0) {
        #pragma unroll
        for (int i = 0; i < 4; i++) {
            int oy = o0 + ty * 4 + i;
            atomicAdd(&g_stats[768 + oy], psum[i]);
            atomicAdd(&g_stats[896 + oy], psq[i]);
        }
    }
}

// ---------------- final feats: apply BN3+ReLU inline, write out + transposed ----------------
__global__ void k_feats(const float* __restrict__ g2, const float* __restrict__ bt2,
                        float* __restrict__ out) {
    int e = blockIdx.x * 256 + threadIdx.x;   // 0 .. 524287
    int b = e >> 18;
    int rem = e & ((C1v * NN) - 1);
    int o = rem >> 11;
    int n = rem & 2047;
    float m = g_stats[768 + o] * (1.f / 4096.f);
    float v = g_stats[896 + o] * (1.f / 4096.f) - m * m;
    float sc = g2[o] * rsqrtf(v + EPSv);
    float sh = bt2[o] - m * sc;
    float f = fmaxf(g_h3[e] * sc + sh, 0.f);
    out[e] = f;
    g_featsT[(size_t)(b * NN + n) * C1v + o] = f;
}

// ---------------- RoI voxel max-pool: smem-resident grid, no atomics, no memset ----------------
__global__ void k_roipool(const float* __restrict__ pts, const float* __restrict__ rois,
                          float* __restrict__ out) {
    extern __shared__ float sg[];            // 125*128 = 16000 floats
    __shared__ int cnt;
    __shared__ int lst[2048];
    int br = blockIdx.x;
    int b = br >> 7;
    int t = threadIdx.x;                     // 128 threads = channels
    for (int i = t; i < 125 * C1v; i += 128) sg[i] = 0.f;
    const float* q = rois + (size_t)br * 7;
    float cx = q[0], cy = q[1], cz = q[2];
    float hx = q[3] * 0.5f, hy = q[4] * 0.5f, hz = q[5] * 0.5f;
    float co = cosf(q[6]), si = sinf(q[6]);
    if (t == 0) cnt = 0;
    __syncthreads();
    const float* P = pts + (size_t)b * NN * 3;
    for (int n = t; n < NN; n += 128) {
        float rx = P[n * 3 + 0] - cx;
        float ry = P[n * 3 + 1] - cy;
        float rz = P[n * 3 + 2] - cz;
        float lx = rx * co + ry * si;
        float ly = -rx * si + ry * co;
        float lz = rz;
        if (fabsf(lx) < hx && fabsf(ly) < hy && fabsf(lz) < hz) {
            int v0 = (int)fminf(fmaxf(floorf((lx + hx) / (2.f * hx) * 5.f), 0.f), 4.f);
            int v1 = (int)fminf(fmaxf(floorf((ly + hy) / (2.f * hy) * 5.f), 0.f), 4.f);
            int v2 = (int)fminf(fmaxf(floorf((lz + hz) / (2.f * hz) * 5.f), 0.f), 4.f);
            int vox = (v0 * 5 + v1) * 5 + v2;
            int pos = atomicAdd(&cnt, 1);
            lst[pos] = (vox << 12) | n;
        }
    }
    __syncthreads();
    const float* F = g_featsT + (size_t)b * NN * C1v;
    int m = cnt;
    for (int e = 0; e < m; e++) {
        int pk = lst[e];
        int n = pk & 4095;
        int vox = pk >> 12;
        float val = F[(size_t)n * C1v + t];
        float* c = &sg[vox * C1v + t];
        *c = fmaxf(*c, val);
    }
    __syncthreads();
    float* og = out + FEATS_SZ + (size_t)br * 125 * C1v;
    for (int i = t; i < 125 * C1v; i += 128) og[i] = sg[i];
}

// ---------------- launch ----------------
extern "C" void kernel_launch(void* const* d_in, const int* in_sizes, int n_in,
                              void* d_out, int out_size) {
    const float* pts    = (const float*)d_in[0];
    const float* feat   = (const float*)d_in[1];
    const float* rois   = (const float*)d_in[2];
    const float* W_mlp  = (const float*)d_in[3];
    const float* g_mlp  = (const float*)d_in[4];
    const float* btm    = (const float*)d_in[5];
    const float* W1     = (const float*)d_in[6];
    const float* b1     = (const float*)d_in[7];
    const float* g1     = (const float*)d_in[8];
    const float* bt1    = (const float*)d_in[9];
    const float* W2     = (const float*)d_in[10];
    const float* b2     = (const float*)d_in[11];
    const float* g2     = (const float*)d_in[12];
    const float* bt2    = (const float*)d_in[13];
    float* out = (float*)d_out;

    cudaFuncSetAttribute(k_roipool, cudaFuncAttributeMaxDynamicSharedMemorySize,
                         125 * C1v * sizeof(float));

    void* statsPtr = nullptr;
    cudaGetSymbolAddress(&statsPtr, g_stats);
    cudaMemsetAsync(statsPtr, 0, 1024 * sizeof(float), 0);

    k_prep<<<452, 256>>>(W_mlp, W1, W2);
    k_neigh<<<dim3(NN / 8, BB), 256>>>(pts);
    k_gemmG<<<dim3(NN / 64, 256 / 64, BB), 256>>>(feat);
    k_gathermax<<<dim3(NN / PPB, BB), 256>>>(pts);
    k_gemm1<<<dim3(NN / 64, C1v / 64, BB), 256>>>(g_mlp, btm, b1);
    k_gemm2<<<dim3(NN / 64, C1v / 64, BB), 256>>>(g1, bt1, b2);
    k_feats<<<FEATS_SZ / 256, 256>>>(g2, bt2, out);
    k_roipool<<<BB * RRoi, 128, 125 * C1v * sizeof(float)>>>(pts, rois, out);
}

// round 3
// speedup vs baseline: 2.5163x; 1.2833x over previous
#include <cuda_runtime.h>
#include <math.h>

// Problem constants
#define BB   2
#define NN   2048
#define RRoi 128
#define CINv 256
#define NSv  16
#define C1v  128
#define RADv 0.3f
#define EPSv 1e-5f
#define FEATS_SZ (BB*C1v*NN)          // 524288
#define GRID_SZ  (BB*RRoi*125*C1v)    // 4096000

// ---------------- scratch ----------------
__device__ int   g_idx[BB*NN*NSv];
__device__ float g_Gt[BB*NN*256];        // [b][j][o]  (o contiguous)
__device__ float g_hmax[BB*256*NN];      // [b][o][n]
__device__ float g_h2[BB*C1v*NN];        // [b][o][n]
__device__ float g_h3[BB*C1v*NN];        // [b][o][n]
__device__ float g_featsT[BB*NN*C1v];    // [b][n][c]
__device__ float g_WfT[256*256];         // [c][o]
__device__ float g_WxT[3*256];           // [k][o]
__device__ float g_W1T[256*C1v];         // [c][o]
__device__ float g_W2T[C1v*C1v];         // [c][o]
__device__ int   g_roilst[BB*RRoi*NN];   // packed (vox<<12)|n per roi
__device__ int   g_roicnt[BB*RRoi];
// stats: [0:256) sum1 [256:512) sq1 [512:640) sum2 [640:768) sq2 [768:896) sum3 [896:1024) sq3
__device__ float g_stats[1024];

// ---------------- fused front: weight transposes + neighbor scan + roi classify ----------------
__global__ void k_front(const float* __restrict__ pts, const float* __restrict__ rois,
                        const float* __restrict__ Wm, const float* __restrict__ W1,
                        const float* __restrict__ W2) {
    __shared__ __align__(16) char sbuf[24576];
    int blk = blockIdx.x;
    if (blk < 452) {
        // ---- weight transposes ----
        int id = blk * 256 + threadIdx.x;
        if (id < 65536) {                      // WfT[c][o] = Wm[o][3+c]
            int o = id & 255, c = id >> 8;
            g_WfT[id] = Wm[o * 259 + 3 + c];
        } else if (id < 66304) {               // WxT[k][o]
            int t = id - 65536; int o = t & 255, k = t >> 8;
            g_WxT[t] = Wm[o * 259 + k];
        } else if (id < 99072) {               // W1T[c][o]
            int t = id - 66304; int o = t & 127, c = t >> 7;
            g_W1T[t] = W1[o * 256 + c];
        } else if (id < 115456) {              // W2T[c][o]
            int t = id - 99072; int o = t & 127, c = t >> 7;
            g_W2T[t] = W2[o * 128 + c];
        }
    } else if (blk < 964) {
        // ---- neighbor search: warp-per-point ballot scan ----
        int q = blk - 452;
        int b = q >> 8, chunk = q & 255;
        float* sx = (float*)sbuf;
        float* sy = sx + NN;
        float* sz = sx + 2 * NN;
        const float* P = pts + (size_t)b * NN * 3;
        for (int j = threadIdx.x; j < NN; j += 256) {
            sx[j] = P[j * 3 + 0]; sy[j] = P[j * 3 + 1]; sz[j] = P[j * 3 + 2];
        }
        __syncthreads();
        int warp = threadIdx.x >> 5, lane = threadIdx.x & 31;
        int i = chunk * 8 + warp;
        float xi = sx[i], yi = sy[i], zi = sz[i];
        int base = (b * NN + i) * NSv;
        const float r2 = RADv * RADv;
        int cnt = 0, f0 = -1;
        for (int j0 = 0; j0 < NN; j0 += 32) {
            int j = j0 + lane;
            float dx = sx[j] - xi, dy = sy[j] - yi, dz = sz[j] - zi;
            bool qq = (dx * dx + dy * dy + dz * dz) < r2;
            unsigned m = __ballot_sync(0xffffffffu, qq);
            if (m) {
                if (f0 < 0) f0 = j0 + __ffs(m) - 1;
                int pos = cnt + __popc(m & ((1u << lane) - 1u));
                if (qq && pos < NSv) g_idx[base + pos] = j;
                cnt += __popc(m);
                if (cnt >= NSv) break;
            }
        }
        if (cnt < NSv) {
            for (int s = cnt + lane; s < NSv; s += 32) g_idx[base + s] = f0;
        }
    } else {
        // ---- roi point-in-box classify ----
        int br = blk - 964;
        int b = br >> 7;
        int* cnt = (int*)sbuf;
        if (threadIdx.x == 0) *cnt = 0;
        __syncthreads();
        const float* qr = rois + (size_t)br * 7;
        float cx = qr[0], cy = qr[1], cz = qr[2];
        float hx = qr[3] * 0.5f, hy = qr[4] * 0.5f, hz = qr[5] * 0.5f;
        float co = cosf(qr[6]), si = sinf(qr[6]);
        const float* P = pts + (size_t)b * NN * 3;
        int* lst = g_roilst + (size_t)br * NN;
        for (int n = threadIdx.x; n < NN; n += 256) {
            float rx = P[n * 3 + 0] - cx;
            float ry = P[n * 3 + 1] - cy;
            float rz = P[n * 3 + 2] - cz;
            float lx = rx * co + ry * si;
            float ly = -rx * si + ry * co;
            float lz = rz;
            if (fabsf(lx) < hx && fabsf(ly) < hy && fabsf(lz) < hz) {
                int v0 = (int)fminf(fmaxf(floorf((lx + hx) / (2.f * hx) * 5.f), 0.f), 4.f);
                int v1 = (int)fminf(fmaxf(floorf((ly + hy) / (2.f * hy) * 5.f), 0.f), 4.f);
                int v2 = (int)fminf(fmaxf(floorf((lz + hz) / (2.f * hz) * 5.f), 0.f), 4.f);
                int vox = (v0 * 5 + v1) * 5 + v2;
                int pos = atomicAdd(cnt, 1);
                lst[pos] = (vox << 12) | n;
            }
        }
        __syncthreads();
        if (threadIdx.x == 0) g_roicnt[br] = *cnt;
    }
}

// ---------------- GEMM: Gt[b][j][o] = sum_c feat[b][c][j] * WfT[c][o] ----------------
__global__ void k_gemmG(const float* __restrict__ feat) {
    __shared__ float As[16][64];  // [kk][j]
    __shared__ float Bs[16][64];  // [kk][o]
    int b = blockIdx.z;
    int j0 = blockIdx.x * 64, o0 = blockIdx.y * 64;
    int tid = threadIdx.x;
    int tx = tid & 15, ty = tid >> 4;
    float acc[4][4] = {};
    for (int k0 = 0; k0 < CINv; k0 += 16) {
        #pragma unroll
        for (int q = 0; q < 4; q++) {
            int l = tid + q * 256;
            int kk = l >> 6, cc = l & 63;
            As[kk][cc] = feat[(size_t)(b * CINv + k0 + kk) * NN + j0 + cc];
            Bs[kk][cc] = g_WfT[(k0 + kk) * 256 + o0 + cc];
        }
        __syncthreads();
        #pragma unroll
        for (int kk = 0; kk < 16; kk++) {
            float4 a4 = *(const float4*)&As[kk][ty * 4];
            float4 b4 = *(const float4*)&Bs[kk][tx * 4];
            float av[4] = {a4.x, a4.y, a4.z, a4.w};
            float bv[4] = {b4.x, b4.y, b4.z, b4.w};
            #pragma unroll
            for (int i = 0; i < 4; i++)
                #pragma unroll
                for (int q = 0; q < 4; q++) acc[i][q] += av[i] * bv[q];
        }
        __syncthreads();
    }
    #pragma unroll
    for (int i = 0; i < 4; i++) {
        float4 st = make_float4(acc[i][0], acc[i][1], acc[i][2], acc[i][3]);
        *(float4*)&g_Gt[(size_t)(b * NN + j0 + ty * 4 + i) * 256 + o0 + tx * 4] = st;
    }
}

// ---------------- gather + xyz MLP + max over samples + BN1 stats (float4 gather) ----------------
#define PPB 8
__global__ void k_gathermax(const float* __restrict__ pts) {
    __shared__ int   sj[PPB * NSv];
    __shared__ float srx[PPB * NSv], sry[PPB * NSv], srz[PPB * NSv];
    __shared__ float stile[256 * (PPB + 1)];
    __shared__ float ssum[4][256], ssq[4][256];
    int b = blockIdx.y;
    int n0 = blockIdx.x * PPB;
    int tid = threadIdx.x;
    if (tid < PPB * NSv) {
        int p = tid >> 4, s = tid & 15;
        int n = n0 + p;
        int j = g_idx[(b * NN + n) * NSv + s];
        sj[tid] = j;
        const float* P = pts + (size_t)b * NN * 3;
        srx[tid] = (P[j * 3 + 0] - P[n * 3 + 0]) / RADv;
        sry[tid] = (P[j * 3 + 1] - P[n * 3 + 1]) / RADv;
        srz[tid] = (P[j * 3 + 2] - P[n * 3 + 2]) / RADv;
    }
    __syncthreads();
    int co = tid & 63;           // channel group: channels co*4 .. co*4+3
    int pg = tid >> 6;           // point group 0..3, handles points pg*2, pg*2+1
    float4 w0 = *(const float4*)&g_WxT[co * 4];
    float4 w1 = *(const float4*)&g_WxT[256 + co * 4];
    float4 w2 = *(const float4*)&g_WxT[512 + co * 4];
    float4 ls = make_float4(0.f, 0.f, 0.f, 0.f);
    float4 lq = make_float4(0.f, 0.f, 0.f, 0.f);
    const float* Gb = g_Gt + (size_t)b * NN * 256;
    #pragma unroll
    for (int pp = 0; pp < 2; pp++) {
        int p = pg * 2 + pp;
        float4 m = make_float4(-3.4e38f, -3.4e38f, -3.4e38f, -3.4e38f);
        #pragma unroll
        for (int s = 0; s < NSv; s++) {
            int e = p * NSv + s;
            int j = sj[e];
            float rx = srx[e], ry = sry[e], rz = srz[e];
            float4 gv = *(const float4*)&Gb[(size_t)j * 256 + co * 4];
            float4 v;
            v.x = gv.x + w0.x * rx + w1.x * ry + w2.x * rz;
            v.y = gv.y + w0.y * rx + w1.y * ry + w2.y * rz;
            v.z = gv.z + w0.z * rx + w1.z * ry + w2.z * rz;
            v.w = gv.w + w0.w * rx + w1.w * ry + w2.w * rz;
            m.x = fmaxf(m.x, v.x); m.y = fmaxf(m.y, v.y);
            m.z = fmaxf(m.z, v.z); m.w = fmaxf(m.w, v.w);
            ls.x += v.x; ls.y += v.y; ls.z += v.z; ls.w += v.w;
            lq.x += v.x * v.x; lq.y += v.y * v.y; lq.z += v.z * v.z; lq.w += v.w * v.w;
        }
        stile[(co * 4 + 0) * (PPB + 1) + p] = m.x;
        stile[(co * 4 + 1) * (PPB + 1) + p] = m.y;
        stile[(co * 4 + 2) * (PPB + 1) + p] = m.z;
        stile[(co * 4 + 3) * (PPB + 1) + p] = m.w;
    }
    ssum[pg][co * 4 + 0] = ls.x; ssum[pg][co * 4 + 1] = ls.y;
    ssum[pg][co * 4 + 2] = ls.z; ssum[pg][co * 4 + 3] = ls.w;
    ssq[pg][co * 4 + 0] = lq.x; ssq[pg][co * 4 + 1] = lq.y;
    ssq[pg][co * 4 + 2] = lq.z; ssq[pg][co * 4 + 3] = lq.w;
    __syncthreads();
    // write hmax tile
    #pragma unroll
    for (int r = 0; r < 256; r += 32) {
        int row = r + (tid >> 3);
        int col = tid & 7;
        g_hmax[(size_t)(b * 256 + row) * NN + n0 + col] = stile[row * (PPB + 1) + col];
    }
    float ts = ssum[0][tid] + ssum[1][tid] + ssum[2][tid] + ssum[3][tid];
    float tq = ssq[0][tid] + ssq[1][tid] + ssq[2][tid] + ssq[3][tid];
    atomicAdd(&g_stats[tid], ts);
    atomicAdd(&g_stats[256 + tid], tq);
}

// ---------------- GEMM1: h2 = b1 + W1 @ relu(bn1(hmax)), fused BN2 stats ----------------
__global__ void k_gemm1(const float* __restrict__ gm, const float* __restrict__ btm,
                        const float* __restrict__ b1) {
    __shared__ float As[16][64];  // [kk][n]
    __shared__ float Bs[16][64];  // [kk][o]
    __shared__ float ssc[256], ssh[256];
    int b = blockIdx.z;
    int n0 = blockIdx.x * 64, o0 = blockIdx.y * 64;
    int tid = threadIdx.x;
    int tx = tid & 15, ty = tid >> 4;
    {
        float m = g_stats[tid] * (1.f / 65536.f);
        float v = g_stats[256 + tid] * (1.f / 65536.f) - m * m;
        float sc = gm[tid] * rsqrtf(v + EPSv);
        ssc[tid] = sc; ssh[tid] = btm[tid] - m * sc;
    }
    __syncthreads();
    float acc[4][4] = {};
    for (int k0 = 0; k0 < 256; k0 += 16) {
        #pragma unroll
        for (int q = 0; q < 4; q++) {
            int l = tid + q * 256;
            int kk = l >> 6, cc = l & 63;
            float v = g_hmax[(size_t)(b * 256 + k0 + kk) * NN + n0 + cc];
            As[kk][cc] = fmaxf(v * ssc[k0 + kk] + ssh[k0 + kk], 0.f);
            Bs[kk][cc] = g_W1T[(k0 + kk) * C1v + o0 + cc];
        }
        __syncthreads();
        #pragma unroll
        for (int kk = 0; kk < 16; kk++) {
            float4 o4 = *(const float4*)&Bs[kk][ty * 4];
            float4 n4 = *(const float4*)&As[kk][tx * 4];
            float ov[4] = {o4.x, o4.y, o4.z, o4.w};
            float nv[4] = {n4.x, n4.y, n4.z, n4.w};
            #pragma unroll
            for (int i = 0; i < 4; i++)
                #pragma unroll
                for (int q = 0; q < 4; q++) acc[i][q] += ov[i] * nv[q];
        }
        __syncthreads();
    }
    float psum[4], psq[4];
    #pragma unroll
    for (int i = 0; i < 4; i++) {
        int oy = o0 + ty * 4 + i;
        float bias = b1[oy];
        float s = 0.f, q = 0.f;
        #pragma unroll
        for (int jn = 0; jn < 4; jn++) {
            float h = acc[i][jn] + bias;
            acc[i][jn] = h; s += h; q += h * h;
        }
        psum[i] = s; psq[i] = q;
        float4 st = make_float4(acc[i][0], acc[i][1], acc[i][2], acc[i][3]);
        *(float4*)&g_h2[(size_t)(b * C1v + oy) * NN + n0 + tx * 4] = st;
    }
    #pragma unroll
    for (int i = 0; i < 4; i++) {
        #pragma unroll
        for (int off = 8; off > 0; off >>= 1) {
            psum[i] += __shfl_down_sync(0xffffffffu, psum[i], off, 16);
            psq[i]  += __shfl_down_sync(0xffffffffu, psq[i],  off, 16);
        }
    }
    if (tx == 0) {
        #pragma unroll
        for (int i = 0; i < 4; i++) {
            int oy = o0 + ty * 4 + i;
            atomicAdd(&g_stats[512 + oy], psum[i]);
            atomicAdd(&g_stats[640 + oy], psq[i]);
        }
    }
}

// ---------------- GEMM2: h3 = b2 + W2 @ relu(bn2(h2)), fused BN3 stats ----------------
__global__ void k_gemm2(const float* __restrict__ g1, const float* __restrict__ bt1,
                        const float* __restrict__ b2) {
    __shared__ float As[16][64];
    __shared__ float Bs[16][64];
    __shared__ float ssc[128], ssh[128];
    int b = blockIdx.z;
    int n0 = blockIdx.x * 64, o0 = blockIdx.y * 64;
    int tid = threadIdx.x;
    int tx = tid & 15, ty = tid >> 4;
    if (tid < 128) {
        float m = g_stats[512 + tid] * (1.f / 4096.f);
        float v = g_stats[640 + tid] * (1.f / 4096.f) - m * m;
        float sc = g1[tid] * rsqrtf(v + EPSv);
        ssc[tid] = sc; ssh[tid] = bt1[tid] - m * sc;
    }
    __syncthreads();
    float acc[4][4] = {};
    for (int k0 = 0; k0 < 128; k0 += 16) {
        #pragma unroll
        for (int q = 0; q < 4; q++) {
            int l = tid + q * 256;
            int kk = l >> 6, cc = l & 63;
            float v = g_h2[(size_t)(b * C1v + k0 + kk) * NN + n0 + cc];
            As[kk][cc] = fmaxf(v * ssc[k0 + kk] + ssh[k0 + kk], 0.f);
            Bs[kk][cc] = g_W2T[(k0 + kk) * C1v + o0 + cc];
        }
        __syncthreads();
        #pragma unroll
        for (int kk = 0; kk < 16; kk++) {
            float4 o4 = *(const float4*)&Bs[kk][ty * 4];
            float4 n4 = *(const float4*)&As[kk][tx * 4];
            float ov[4] = {o4.x, o4.y, o4.z, o4.w};
            float nv[4] = {n4.x, n4.y, n4.z, n4.w};
            #pragma unroll
            for (int i = 0; i < 4; i++)
                #pragma unroll
                for (int q = 0; q < 4; q++) acc[i][q] += ov[i] * nv[q];
        }
        __syncthreads();
    }
    float psum[4], psq[4];
    #pragma unroll
    for (int i = 0; i < 4; i++) {
        int oy = o0 + ty * 4 + i;
        float bias = b2[oy];
        float s = 0.f, q = 0.f;
        #pragma unroll
        for (int jn = 0; jn < 4; jn++) {
            float h = acc[i][jn] + bias;
            acc[i][jn] = h; s += h; q += h * h;
        }
        psum[i] = s; psq[i] = q;
        float4 st = make_float4(acc[i][0], acc[i][1], acc[i][2], acc[i][3]);
        *(float4*)&g_h3[(size_t)(b * C1v + oy) * NN + n0 + tx * 4] = st;
    }
    #pragma unroll
    for (int i = 0; i < 4; i++) {
        #pragma unroll
        for (int off = 8; off > 0; off >>= 1) {
            psum[i] += __shfl_down_sync(0xffffffffu, psum[i], off, 16);
            psq[i]  += __shfl_down_sync(0xffffffffu, psq[i],  off, 16);
        }
    }
    if (tx == 0) {
        #pragma unroll
        for (int i = 0; i < 4; i++) {
            int oy = o0 + ty * 4 + i;
            atomicAdd(&g_stats[768 + oy], psum[i]);
            atomicAdd(&g_stats[896 + oy], psq[i]);
        }
    }
}

// ---------------- final feats: BN3+ReLU, tiled transpose (both writes coalesced) ----------------
__global__ void k_feats(const float* __restrict__ g2, const float* __restrict__ bt2,
                        float* __restrict__ out) {
    __shared__ float t[32][33];
    __shared__ float ssc[32], ssh[32];
    int b = blockIdx.z;
    int n0 = blockIdx.x * 32, o0 = blockIdx.y * 32;
    int tid = threadIdx.x;
    int tx = tid & 31, ty = tid >> 5;          // 32x8
    if (tid < 32) {
        int o = o0 + tid;
        float m = g_stats[768 + o] * (1.f / 4096.f);
        float v = g_stats[896 + o] * (1.f / 4096.f) - m * m;
        float sc = g2[o] * rsqrtf(v + EPSv);
        ssc[tid] = sc; ssh[tid] = bt2[o] - m * sc;
    }
    __syncthreads();
    #pragma unroll
    for (int r = 0; r < 4; r++) {
        int oo = ty + r * 8;
        int o = o0 + oo;
        size_t e = (size_t)(b * C1v + o) * NN + n0 + tx;
        float f = fmaxf(g_h3[e] * ssc[oo] + ssh[oo], 0.f);
        out[e] = f;
        t[oo][tx] = f;
    }
    __syncthreads();
    #pragma unroll
    for (int r = 0; r < 4; r++) {
        int nn = ty + r * 8;
        g_featsT[(size_t)(b * NN + n0 + nn) * C1v + o0 + tx] = t[tx][nn];
    }
}

// ---------------- RoI voxel max-pool: smem grid, precomputed lists ----------------
__global__ void k_roipool(float* __restrict__ out) {
    extern __shared__ float sg[];            // 125*128 floats
    int br = blockIdx.x;
    int b = br >> 7;
    int t = threadIdx.x;                     // 128 threads = channels
    for (int i = t; i < 125 * C1v; i += 128) sg[i] = 0.f;
    __syncthreads();
    const float* F = g_featsT + (size_t)b * NN * C1v;
    const int* lst = g_roilst + (size_t)br * NN;
    int m = g_roicnt[br];
    for (int e = 0; e < m; e++) {
        int pk = lst[e];
        int n = pk & 4095;
        int vox = pk >> 12;
        float val = F[(size_t)n * C1v + t];
        float* c = &sg[vox * C1v + t];
        *c = fmaxf(*c, val);
    }
    __syncthreads();
    float* og = out + FEATS_SZ + (size_t)br * 125 * C1v;
    for (int i = t; i < 125 * C1v; i += 128) og[i] = sg[i];
}

// ---------------- launch ----------------
extern "C" void kernel_launch(void* const* d_in, const int* in_sizes, int n_in,
                              void* d_out, int out_size) {
    const float* pts    = (const float*)d_in[0];
    const float* feat   = (const float*)d_in[1];
    const float* rois   = (const float*)d_in[2];
    const float* W_mlp  = (const float*)d_in[3];
    const float* g_mlp  = (const float*)d_in[4];
    const float* btm    = (const float*)d_in[5];
    const float* W1     = (const float*)d_in[6];
    const float* b1     = (const float*)d_in[7];
    const float* g1     = (const float*)d_in[8];
    const float* bt1    = (const float*)d_in[9];
    const float* W2     = (const float*)d_in[10];
    const float* b2     = (const float*)d_in[11];
    const float* g2     = (const float*)d_in[12];
    const float* bt2    = (const float*)d_in[13];
    float* out = (float*)d_out;

    cudaFuncSetAttribute(k_roipool, cudaFuncAttributeMaxDynamicSharedMemorySize,
                         125 * C1v * sizeof(float));

    void* statsPtr = nullptr;
    cudaGetSymbolAddress(&statsPtr, g_stats);
    cudaMemsetAsync(statsPtr, 0, 1024 * sizeof(float), 0);

    k_front<<<1220, 256>>>(pts, rois, W_mlp, W1, W2);
    k_gemmG<<<dim3(NN / 64, 256 / 64, BB), 256>>>(feat);
    k_gathermax<<<dim3(NN / PPB, BB), 256>>>(pts);
    k_gemm1<<<dim3(NN / 64, C1v / 64, BB), 256>>>(g_mlp, btm, b1);
    k_gemm2<<<dim3(NN / 64, C1v / 64, BB), 256>>>(g1, bt1, b2);
    k_feats<<<dim3(NN / 32, C1v / 32, BB), 256>>>(g2, bt2, out);
    k_roipool<<<BB * RRoi, 128, 125 * C1v * sizeof(float)>>>(out);
}

// round 4
// speedup vs baseline: 2.8669x; 1.1393x over previous
#include <cuda_runtime.h>
#include <math.h>

// Problem constants
#define BB   2
#define NN   2048
#define RRoi 128
#define CINv 256
#define NSv  16
#define C1v  128
#define RADv 0.3f
#define EPSv 1e-5f
#define FEATS_SZ (BB*C1v*NN)          // 524288
#define GRID_SZ  (BB*RRoi*125*C1v)    // 4096000

// ---------------- scratch ----------------
__device__ int   g_idx[BB*NN*NSv];
__device__ float g_Gt[BB*NN*256];        // [b][j][o]  (o contiguous)
__device__ float g_hmax[BB*256*NN];      // [b][o][n]
__device__ float g_h2[BB*C1v*NN];        // [b][o][n]
__device__ float g_h3[BB*C1v*NN];        // [b][o][n]
__device__ float g_featsT[BB*NN*C1v];    // [b][n][c]
__device__ float g_WfT[256*256];         // [c][o]
__device__ float g_WxT[3*256];           // [k][o]
__device__ float g_W1T[256*C1v];         // [c][o]
__device__ float g_W2T[C1v*C1v];         // [c][o]
__device__ int   g_roilst[BB*RRoi*NN];   // packed (vox<<12)|n per roi
__device__ int   g_roicnt[BB*RRoi];
// stats: [0:256) sum1 [256:512) sq1 [512:640) sum2 [640:768) sq2 [768:896) sum3 [896:1024) sq3
__device__ float g_stats[1024];

// ---------------- fused front: weight transposes + neighbor scan + roi classify ----------------
__global__ void k_front(const float* __restrict__ pts, const float* __restrict__ rois,
                        const float* __restrict__ Wm, const float* __restrict__ W1,
                        const float* __restrict__ W2) {
    __shared__ __align__(16) char sbuf[24576];
    int blk = blockIdx.x;
    if (blk < 452) {
        int id = blk * 256 + threadIdx.x;
        if (id < 65536) {                      // WfT[c][o] = Wm[o][3+c]
            int o = id & 255, c = id >> 8;
            g_WfT[id] = Wm[o * 259 + 3 + c];
        } else if (id < 66304) {               // WxT[k][o]
            int t = id - 65536; int o = t & 255, k = t >> 8;
            g_WxT[t] = Wm[o * 259 + k];
        } else if (id < 99072) {               // W1T[c][o]
            int t = id - 66304; int o = t & 127, c = t >> 7;
            g_W1T[t] = W1[o * 256 + c];
        } else if (id < 115456) {              // W2T[c][o]
            int t = id - 99072; int o = t & 127, c = t >> 7;
            g_W2T[t] = W2[o * 128 + c];
        }
    } else if (blk < 964) {
        // ---- neighbor search: warp-per-point ballot scan ----
        int q = blk - 452;
        int b = q >> 8, chunk = q & 255;
        float* sx = (float*)sbuf;
        float* sy = sx + NN;
        float* sz = sx + 2 * NN;
        const float* P = pts + (size_t)b * NN * 3;
        for (int j = threadIdx.x; j < NN; j += 256) {
            sx[j] = P[j * 3 + 0]; sy[j] = P[j * 3 + 1]; sz[j] = P[j * 3 + 2];
        }
        __syncthreads();
        int warp = threadIdx.x >> 5, lane = threadIdx.x & 31;
        int i = chunk * 8 + warp;
        float xi = sx[i], yi = sy[i], zi = sz[i];
        int base = (b * NN + i) * NSv;
        const float r2 = RADv * RADv;
        int cnt = 0, f0 = -1;
        for (int j0 = 0; j0 < NN; j0 += 32) {
            int j = j0 + lane;
            float dx = sx[j] - xi, dy = sy[j] - yi, dz = sz[j] - zi;
            bool qq = (dx * dx + dy * dy + dz * dz) < r2;
            unsigned m = __ballot_sync(0xffffffffu, qq);
            if (m) {
                if (f0 < 0) f0 = j0 + __ffs(m) - 1;
                int pos = cnt + __popc(m & ((1u << lane) - 1u));
                if (qq && pos < NSv) g_idx[base + pos] = j;
                cnt += __popc(m);
                if (cnt >= NSv) break;
            }
        }
        if (cnt < NSv) {
            for (int s = cnt + lane; s < NSv; s += 32) g_idx[base + s] = f0;
        }
    } else {
        // ---- roi point-in-box classify ----
        int br = blk - 964;
        int b = br >> 7;
        int* cnt = (int*)sbuf;
        if (threadIdx.x == 0) *cnt = 0;
        __syncthreads();
        const float* qr = rois + (size_t)br * 7;
        float cx = qr[0], cy = qr[1], cz = qr[2];
        float hx = qr[3] * 0.5f, hy = qr[4] * 0.5f, hz = qr[5] * 0.5f;
        float co = cosf(qr[6]), si = sinf(qr[6]);
        const float* P = pts + (size_t)b * NN * 3;
        int* lst = g_roilst + (size_t)br * NN;
        for (int n = threadIdx.x; n < NN; n += 256) {
            float rx = P[n * 3 + 0] - cx;
            float ry = P[n * 3 + 1] - cy;
            float rz = P[n * 3 + 2] - cz;
            float lx = rx * co + ry * si;
            float ly = -rx * si + ry * co;
            float lz = rz;
            if (fabsf(lx) < hx && fabsf(ly) < hy && fabsf(lz) < hz) {
                int v0 = (int)fminf(fmaxf(floorf((lx + hx) / (2.f * hx) * 5.f), 0.f), 4.f);
                int v1 = (int)fminf(fmaxf(floorf((ly + hy) / (2.f * hy) * 5.f), 0.f), 4.f);
                int v2 = (int)fminf(fmaxf(floorf((lz + hz) / (2.f * hz) * 5.f), 0.f), 4.f);
                int vox = (v0 * 5 + v1) * 5 + v2;
                int pos = atomicAdd(cnt, 1);
                lst[pos] = (vox << 12) | n;
            }
        }
        __syncthreads();
        if (threadIdx.x == 0) g_roicnt[br] = *cnt;
    }
}

// ---------------- GEMM: Gt[b][j][o] = sum_c feat[b][c][j] * WfT[c][o]  (double-buffered) ----------------
__global__ void k_gemmG(const float* __restrict__ feat) {
    __shared__ float As[2][16][64];  // [kk][j]
    __shared__ float Bs[2][16][64];  // [kk][o]
    int b = blockIdx.z;
    int j0 = blockIdx.x * 64, o0 = blockIdx.y * 64;
    int tid = threadIdx.x;
    int tx = tid & 15, ty = tid >> 4;
    int lk = tid >> 4, lc = (tid & 15) * 4;
    const float* Asrc = feat + (size_t)(b * CINv) * NN;
    *(float4*)&As[0][lk][lc] = *(const float4*)&Asrc[(size_t)lk * NN + j0 + lc];
    *(float4*)&Bs[0][lk][lc] = *(const float4*)&g_WfT[lk * 256 + o0 + lc];
    __syncthreads();
    float acc[4][4] = {};
    int buf = 0;
    for (int t = 0; t < 16; t++) {
        float4 a_reg, b_reg;
        if (t < 15) {
            int k0 = (t + 1) * 16;
            a_reg = *(const float4*)&Asrc[(size_t)(k0 + lk) * NN + j0 + lc];
            b_reg = *(const float4*)&g_WfT[(k0 + lk) * 256 + o0 + lc];
        }
        #pragma unroll
        for (int kk = 0; kk < 16; kk++) {
            float4 a4 = *(const float4*)&As[buf][kk][ty * 4];
            float4 b4 = *(const float4*)&Bs[buf][kk][tx * 4];
            float av[4] = {a4.x, a4.y, a4.z, a4.w};
            float bv[4] = {b4.x, b4.y, b4.z, b4.w};
            #pragma unroll
            for (int i = 0; i < 4; i++)
                #pragma unroll
                for (int q = 0; q < 4; q++) acc[i][q] += av[i] * bv[q];
        }
        if (t < 15) {
            *(float4*)&As[buf ^ 1][lk][lc] = a_reg;
            *(float4*)&Bs[buf ^ 1][lk][lc] = b_reg;
        }
        __syncthreads();
        buf ^= 1;
    }
    #pragma unroll
    for (int i = 0; i < 4; i++) {
        float4 st = make_float4(acc[i][0], acc[i][1], acc[i][2], acc[i][3]);
        *(float4*)&g_Gt[(size_t)(b * NN + j0 + ty * 4 + i) * 256 + o0 + tx * 4] = st;
    }
}

// ---------------- gather + xyz MLP + max over samples + BN1 stats (float4 gather) ----------------
#define PPB 8
__global__ void k_gathermax(const float* __restrict__ pts) {
    __shared__ int   sj[PPB * NSv];
    __shared__ float srx[PPB * NSv], sry[PPB * NSv], srz[PPB * NSv];
    __shared__ float stile[256 * (PPB + 1)];
    __shared__ float ssum[4][256], ssq[4][256];
    int b = blockIdx.y;
    int n0 = blockIdx.x * PPB;
    int tid = threadIdx.x;
    if (tid < PPB * NSv) {
        int p = tid >> 4, s = tid & 15;
        int n = n0 + p;
        int j = g_idx[(b * NN + n) * NSv + s];
        sj[tid] = j;
        const float* P = pts + (size_t)b * NN * 3;
        srx[tid] = (P[j * 3 + 0] - P[n * 3 + 0]) / RADv;
        sry[tid] = (P[j * 3 + 1] - P[n * 3 + 1]) / RADv;
        srz[tid] = (P[j * 3 + 2] - P[n * 3 + 2]) / RADv;
    }
    __syncthreads();
    int co = tid & 63;
    int pg = tid >> 6;
    float4 w0 = *(const float4*)&g_WxT[co * 4];
    float4 w1 = *(const float4*)&g_WxT[256 + co * 4];
    float4 w2 = *(const float4*)&g_WxT[512 + co * 4];
    float4 ls = make_float4(0.f, 0.f, 0.f, 0.f);
    float4 lq = make_float4(0.f, 0.f, 0.f, 0.f);
    const float* Gb = g_Gt + (size_t)b * NN * 256;
    #pragma unroll
    for (int pp = 0; pp < 2; pp++) {
        int p = pg * 2 + pp;
        float4 m = make_float4(-3.4e38f, -3.4e38f, -3.4e38f, -3.4e38f);
        #pragma unroll
        for (int s = 0; s < NSv; s++) {
            int e = p * NSv + s;
            int j = sj[e];
            float rx = srx[e], ry = sry[e], rz = srz[e];
            float4 gv = *(const float4*)&Gb[(size_t)j * 256 + co * 4];
            float4 v;
            v.x = gv.x + w0.x * rx + w1.x * ry + w2.x * rz;
            v.y = gv.y + w0.y * rx + w1.y * ry + w2.y * rz;
            v.z = gv.z + w0.z * rx + w1.z * ry + w2.z * rz;
            v.w = gv.w + w0.w * rx + w1.w * ry + w2.w * rz;
            m.x = fmaxf(m.x, v.x); m.y = fmaxf(m.y, v.y);
            m.z = fmaxf(m.z, v.z); m.w = fmaxf(m.w, v.w);
            ls.x += v.x; ls.y += v.y; ls.z += v.z; ls.w += v.w;
            lq.x += v.x * v.x; lq.y += v.y * v.y; lq.z += v.z * v.z; lq.w += v.w * v.w;
        }
        stile[(co * 4 + 0) * (PPB + 1) + p] = m.x;
        stile[(co * 4 + 1) * (PPB + 1) + p] = m.y;
        stile[(co * 4 + 2) * (PPB + 1) + p] = m.z;
        stile[(co * 4 + 3) * (PPB + 1) + p] = m.w;
    }
    ssum[pg][co * 4 + 0] = ls.x; ssum[pg][co * 4 + 1] = ls.y;
    ssum[pg][co * 4 + 2] = ls.z; ssum[pg][co * 4 + 3] = ls.w;
    ssq[pg][co * 4 + 0] = lq.x; ssq[pg][co * 4 + 1] = lq.y;
    ssq[pg][co * 4 + 2] = lq.z; ssq[pg][co * 4 + 3] = lq.w;
    __syncthreads();
    #pragma unroll
    for (int r = 0; r < 256; r += 32) {
        int row = r + (tid >> 3);
        int col = tid & 7;
        g_hmax[(size_t)(b * 256 + row) * NN + n0 + col] = stile[row * (PPB + 1) + col];
    }
    float ts = ssum[0][tid] + ssum[1][tid] + ssum[2][tid] + ssum[3][tid];
    float tq = ssq[0][tid] + ssq[1][tid] + ssq[2][tid] + ssq[3][tid];
    atomicAdd(&g_stats[tid], ts);
    atomicAdd(&g_stats[256 + tid], tq);
}

// ---------------- GEMM1: h2 = b1 + W1 @ relu(bn1(hmax)), fused BN2 stats (double-buffered) ----------------
__global__ void k_gemm1(const float* __restrict__ gm, const float* __restrict__ btm,
                        const float* __restrict__ b1) {
    __shared__ float As[2][16][64];  // [kk][n]
    __shared__ float Bs[2][16][64];  // [kk][o]
    __shared__ float ssc[256], ssh[256];
    int b = blockIdx.z;
    int n0 = blockIdx.x * 64, o0 = blockIdx.y * 64;
    int tid = threadIdx.x;
    int tx = tid & 15, ty = tid >> 4;
    int lk = tid >> 4, lc = (tid & 15) * 4;
    {
        float m = g_stats[tid] * (1.f / 65536.f);
        float v = g_stats[256 + tid] * (1.f / 65536.f) - m * m;
        float sc = gm[tid] * rsqrtf(v + EPSv);
        ssc[tid] = sc; ssh[tid] = btm[tid] - m * sc;
    }
    __syncthreads();
    const float* Asrc = g_hmax + (size_t)(b * 256) * NN;
    {
        float4 a = *(const float4*)&Asrc[(size_t)lk * NN + n0 + lc];
        float sc = ssc[lk], sh = ssh[lk];
        a.x = fmaxf(a.x * sc + sh, 0.f); a.y = fmaxf(a.y * sc + sh, 0.f);
        a.z = fmaxf(a.z * sc + sh, 0.f); a.w = fmaxf(a.w * sc + sh, 0.f);
        *(float4*)&As[0][lk][lc] = a;
        *(float4*)&Bs[0][lk][lc] = *(const float4*)&g_W1T[lk * C1v + o0 + lc];
    }
    __syncthreads();
    float acc[4][4] = {};
    int buf = 0;
    for (int t = 0; t < 16; t++) {
        float4 a_reg, b_reg;
        if (t < 15) {
            int k0 = (t + 1) * 16;
            a_reg = *(const float4*)&Asrc[(size_t)(k0 + lk) * NN + n0 + lc];
            b_reg = *(const float4*)&g_W1T[(k0 + lk) * C1v + o0 + lc];
        }
        #pragma unroll
        for (int kk = 0; kk < 16; kk++) {
            float4 o4 = *(const float4*)&Bs[buf][kk][ty * 4];
            float4 n4 = *(const float4*)&As[buf][kk][tx * 4];
            float ov[4] = {o4.x, o4.y, o4.z, o4.w};
            float nv[4] = {n4.x, n4.y, n4.z, n4.w};
            #pragma unroll
            for (int i = 0; i < 4; i++)
                #pragma unroll
                for (int q = 0; q < 4; q++) acc[i][q] += ov[i] * nv[q];
        }
        if (t < 15) {
            int k0 = (t + 1) * 16;
            float sc = ssc[k0 + lk], sh = ssh[k0 + lk];
            a_reg.x = fmaxf(a_reg.x * sc + sh, 0.f); a_reg.y = fmaxf(a_reg.y * sc + sh, 0.f);
            a_reg.z = fmaxf(a_reg.z * sc + sh, 0.f); a_reg.w = fmaxf(a_reg.w * sc + sh, 0.f);
            *(float4*)&As[buf ^ 1][lk][lc] = a_reg;
            *(float4*)&Bs[buf ^ 1][lk][lc] = b_reg;
        }
        __syncthreads();
        buf ^= 1;
    }
    float psum[4], psq[4];
    #pragma unroll
    for (int i = 0; i < 4; i++) {
        int oy = o0 + ty * 4 + i;
        float bias = b1[oy];
        float s = 0.f, q = 0.f;
        #pragma unroll
        for (int jn = 0; jn < 4; jn++) {
            float h = acc[i][jn] + bias;
            acc[i][jn] = h; s += h; q += h * h;
        }
        psum[i] = s; psq[i] = q;
        float4 st = make_float4(acc[i][0], acc[i][1], acc[i][2], acc[i][3]);
        *(float4*)&g_h2[(size_t)(b * C1v + oy) * NN + n0 + tx * 4] = st;
    }
    #pragma unroll
    for (int i = 0; i < 4; i++) {
        #pragma unroll
        for (int off = 8; off > 0; off >>= 1) {
            psum[i] += __shfl_down_sync(0xffffffffu, psum[i], off, 16);
            psq[i]  += __shfl_down_sync(0xffffffffu, psq[i],  off, 16);
        }
    }
    if (tx == 0) {
        #pragma unroll
        for (int i = 0; i < 4; i++) {
            int oy = o0 + ty * 4 + i;
            atomicAdd(&g_stats[512 + oy], psum[i]);
            atomicAdd(&g_stats[640 + oy], psq[i]);
        }
    }
}

// ---------------- GEMM2: h3 = b2 + W2 @ relu(bn2(h2)), fused BN3 stats (double-buffered) ----------------
__global__ void k_gemm2(const float* __restrict__ g1, const float* __restrict__ bt1,
                        const float* __restrict__ b2) {
    __shared__ float As[2][16][64];
    __shared__ float Bs[2][16][64];
    __shared__ float ssc[128], ssh[128];
    int b = blockIdx.z;
    int n0 = blockIdx.x * 64, o0 = blockIdx.y * 64;
    int tid = threadIdx.x;
    int tx = tid & 15, ty = tid >> 4;
    int lk = tid >> 4, lc = (tid & 15) * 4;
    if (tid < 128) {
        float m = g_stats[512 + tid] * (1.f / 4096.f);
        float v = g_stats[640 + tid] * (1.f / 4096.f) - m * m;
        float sc = g1[tid] * rsqrtf(v + EPSv);
        ssc[tid] = sc; ssh[tid] = bt1[tid] - m * sc;
    }
    __syncthreads();
    const float* Asrc = g_h2 + (size_t)(b * C1v) * NN;
    {
        float4 a = *(const float4*)&Asrc[(size_t)lk * NN + n0 + lc];
        float sc = ssc[lk], sh = ssh[lk];
        a.x = fmaxf(a.x * sc + sh, 0.f); a.y = fmaxf(a.y * sc + sh, 0.f);
        a.z = fmaxf(a.z * sc + sh, 0.f); a.w = fmaxf(a.w * sc + sh, 0.f);
        *(float4*)&As[0][lk][lc] = a;
        *(float4*)&Bs[0][lk][lc] = *(const float4*)&g_W2T[lk * C1v + o0 + lc];
    }
    __syncthreads();
    float acc[4][4] = {};
    int buf = 0;
    for (int t = 0; t < 8; t++) {
        float4 a_reg, b_reg;
        if (t < 7) {
            int k0 = (t + 1) * 16;
            a_reg = *(const float4*)&Asrc[(size_t)(k0 + lk) * NN + n0 + lc];
            b_reg = *(const float4*)&g_W2T[(k0 + lk) * C1v + o0 + lc];
        }
        #pragma unroll
        for (int kk = 0; kk < 16; kk++) {
            float4 o4 = *(const float4*)&Bs[buf][kk][ty * 4];
            float4 n4 = *(const float4*)&As[buf][kk][tx * 4];
            float ov[4] = {o4.x, o4.y, o4.z, o4.w};
            float nv[4] = {n4.x, n4.y, n4.z, n4.w};
            #pragma unroll
            for (int i = 0; i < 4; i++)
                #pragma unroll
                for (int q = 0; q < 4; q++) acc[i][q] += ov[i] * nv[q];
        }
        if (t < 7) {
            int k0 = (t + 1) * 16;
            float sc = ssc[k0 + lk], sh = ssh[k0 + lk];
            a_reg.x = fmaxf(a_reg.x * sc + sh, 0.f); a_reg.y = fmaxf(a_reg.y * sc + sh, 0.f);
            a_reg.z = fmaxf(a_reg.z * sc + sh, 0.f); a_reg.w = fmaxf(a_reg.w * sc + sh, 0.f);
            *(float4*)&As[buf ^ 1][lk][lc] = a_reg;
            *(float4*)&Bs[buf ^ 1][lk][lc] = b_reg;
        }
        __syncthreads();
        buf ^= 1;
    }
    float psum[4], psq[4];
    #pragma unroll
    for (int i = 0; i < 4; i++) {
        int oy = o0 + ty * 4 + i;
        float bias = b2[oy];
        float s = 0.f, q = 0.f;
        #pragma unroll
        for (int jn = 0; jn < 4; jn++) {
            float h = acc[i][jn] + bias;
            acc[i][jn] = h; s += h; q += h * h;
        }
        psum[i] = s; psq[i] = q;
        float4 st = make_float4(acc[i][0], acc[i][1], acc[i][2], acc[i][3]);
        *(float4*)&g_h3[(size_t)(b * C1v + oy) * NN + n0 + tx * 4] = st;
    }
    #pragma unroll
    for (int i = 0; i < 4; i++) {
        #pragma unroll
        for (int off = 8; off > 0; off >>= 1) {
            psum[i] += __shfl_down_sync(0xffffffffu, psum[i], off, 16);
            psq[i]  += __shfl_down_sync(0xffffffffu, psq[i],  off, 16);
        }
    }
    if (tx == 0) {
        #pragma unroll
        for (int i = 0; i < 4; i++) {
            int oy = o0 + ty * 4 + i;
            atomicAdd(&g_stats[768 + oy], psum[i]);
            atomicAdd(&g_stats[896 + oy], psq[i]);
        }
    }
}

// ---------------- final feats: BN3+ReLU, tiled transpose (both writes coalesced) ----------------
__global__ void k_feats(const float* __restrict__ g2, const float* __restrict__ bt2,
                        float* __restrict__ out) {
    __shared__ float t[32][33];
    __shared__ float ssc[32], ssh[32];
    int b = blockIdx.z;
    int n0 = blockIdx.x * 32, o0 = blockIdx.y * 32;
    int tid = threadIdx.x;
    int tx = tid & 31, ty = tid >> 5;          // 32x8
    if (tid < 32) {
        int o = o0 + tid;
        float m = g_stats[768 + o] * (1.f / 4096.f);
        float v = g_stats[896 + o] * (1.f / 4096.f) - m * m;
        float sc = g2[o] * rsqrtf(v + EPSv);
        ssc[tid] = sc; ssh[tid] = bt2[o] - m * sc;
    }
    __syncthreads();
    #pragma unroll
    for (int r = 0; r < 4; r++) {
        int oo = ty + r * 8;
        int o = o0 + oo;
        size_t e = (size_t)(b * C1v + o) * NN + n0 + tx;
        float f = fmaxf(g_h3[e] * ssc[oo] + ssh[oo], 0.f);
        out[e] = f;
        t[oo][tx] = f;
    }
    __syncthreads();
    #pragma unroll
    for (int r = 0; r < 4; r++) {
        int nn = ty + r * 8;
        g_featsT[(size_t)(b * NN + n0 + nn) * C1v + o0 + tx] = t[tx][nn];
    }
}

// ---------------- RoI voxel max-pool: smem grid, parallel over points via smem atomicMax ----------------
__global__ void k_roipool(float* __restrict__ out) {
    extern __shared__ float sg[];            // 125*128 floats
    int br = blockIdx.x;
    int b = br >> 7;
    int t = threadIdx.x;                     // 512
    for (int i = t; i < 125 * C1v / 4; i += 512)
        ((float4*)sg)[i] = make_float4(0.f, 0.f, 0.f, 0.f);
    __syncthreads();
    const float* F = g_featsT + (size_t)b * NN * C1v;
    const int* lst = g_roilst + (size_t)br * NN;
    int m = g_roicnt[br];
    int ch = t & 127;
    int slot = t >> 7;                       // 0..3
    for (int e = slot; e < m; e += 4) {
        int pk = lst[e];
        int n = pk & 4095;
        int vox = pk >> 12;
        float val = F[(size_t)n * C1v + ch];
        atomicMax((int*)&sg[vox * C1v + ch], __float_as_int(val));
    }
    __syncthreads();
    float4* og = (float4*)(out + FEATS_SZ + (size_t)br * 125 * C1v);
    for (int i = t; i < 125 * C1v / 4; i += 512) og[i] = ((float4*)sg)[i];
}

// ---------------- launch ----------------
extern "C" void kernel_launch(void* const* d_in, const int* in_sizes, int n_in,
                              void* d_out, int out_size) {
    const float* pts    = (const float*)d_in[0];
    const float* feat   = (const float*)d_in[1];
    const float* rois   = (const float*)d_in[2];
    const float* W_mlp  = (const float*)d_in[3];
    const float* g_mlp  = (const float*)d_in[4];
    const float* btm    = (const float*)d_in[5];
    const float* W1     = (const float*)d_in[6];
    const float* b1     = (const float*)d_in[7];
    const float* g1     = (const float*)d_in[8];
    const float* bt1    = (const float*)d_in[9];
    const float* W2     = (const float*)d_in[10];
    const float* b2     = (const float*)d_in[11];
    const float* g2     = (const float*)d_in[12];
    const float* bt2    = (const float*)d_in[13];
    float* out = (float*)d_out;

    cudaFuncSetAttribute(k_roipool, cudaFuncAttributeMaxDynamicSharedMemorySize,
                         125 * C1v * sizeof(float));

    void* statsPtr = nullptr;
    cudaGetSymbolAddress(&statsPtr, g_stats);
    cudaMemsetAsync(statsPtr, 0, 1024 * sizeof(float), 0);

    k_front<<<1220, 256>>>(pts, rois, W_mlp, W1, W2);
    k_gemmG<<<dim3(NN / 64, 256 / 64, BB), 256>>>(feat);
    k_gathermax<<<dim3(NN / PPB, BB), 256>>>(pts);
    k_gemm1<<<dim3(NN / 64, C1v / 64, BB), 256>>>(g_mlp, btm, b1);
    k_gemm2<<<dim3(NN / 64, C1v / 64, BB), 256>>>(g1, bt1, b2);
    k_feats<<<dim3(NN / 32, C1v / 32, BB), 256>>>(g2, bt2, out);
    k_roipool<<<BB * RRoi, 512, 125 * C1v * sizeof(float)>>>(out);
}